// round 9
// baseline (speedup 1.0000x reference)
#include <cuda_runtime.h>
#include <math.h>
#include <stdint.h>

// Problem constants
#define DD 256
#define PP 64
#define TINV 10.0f

// Output offsets (floats): routing(65536) | routes(67108864) | tw(65536) | ps(4194304)
#define OFF_ROUTING 0LL
#define OFF_ROUTES  65536LL
#define OFF_TW      67174400LL
#define OFF_PS      67239936LL

#define N_GEMM 512          // 65536 rows / 128 rows per tile
#define GRID_TOTAL 8768

// smem (floats):
//  [0,64)    normInv
//  [64,192)  sInv
//  [256, 256+128*68)        sA  (fp32, pitch 68 — conflict-free A-frag loads)
//  [8960, 8960+64*68*2)     sB2 (uint2 {tf32hi, tf32lo}, pitch 68 uint2 — conflict-free LDS.64)
// epilogue overlay: sS[128][66] at sA (8448 <= 8704 floats)
#define PITCH 68
#define SA_OFF 256
#define SB2_OFF (SA_OFF + 128 * PITCH)     // 8960
#define PITCH_B2 68                        // uint2 elements per row (>= 64 needed!)
#define SMEM_FLOATS (SB2_OFF + 64 * PITCH_B2 * 2)
#define SMEM_BYTES (SMEM_FLOATS * 4)       // 70656 B -> 3 CTAs/SM

// ---- tf32 helpers ----
__device__ __forceinline__ unsigned f2tf(float x) {
    unsigned r;
    asm("cvt.rna.tf32.f32 %0, %1;" : "=r"(r) : "f"(x));
    return r;
}
__device__ __forceinline__ void split_tf32(float x, unsigned& hi, unsigned& lo) {
    hi = f2tf(x);
    lo = f2tf(x - __uint_as_float(hi));
}
__device__ __forceinline__ void mma_tf32(float* c,
                                         unsigned a0, unsigned a1, unsigned a2, unsigned a3,
                                         unsigned b0, unsigned b1) {
    asm volatile(
        "mma.sync.aligned.m16n8k8.row.col.f32.tf32.tf32.f32 "
        "{%0,%1,%2,%3}, {%4,%5,%6,%7}, {%8,%9}, {%0,%1,%2,%3};"
        : "+f"(c[0]), "+f"(c[1]), "+f"(c[2]), "+f"(c[3])
        : "r"(a0), "r"(a1), "r"(a2), "r"(a3), "r"(b0), "r"(b1));
}

// ---------------------------------------------------------------------------
// Single fused kernel: TF32-mma GEMM+softmax tiles interleaved with fill CTAs.
// ---------------------------------------------------------------------------
__global__ __launch_bounds__(256, 3)
void fused_kernel(const float* __restrict__ states,
                  const float* __restrict__ patterns,
                  const float* __restrict__ tw_in,
                  float* __restrict__ out) {
    extern __shared__ float smem[];
    int bid = blockIdx.x;
    int tid = threadIdx.x;

    bool isGemm = (bid < 17 * N_GEMM) && (bid % 17 == 0);

    if (!isGemm) {
        long long fillIdx = (bid < 17 * N_GEMM) ? (bid - (bid + 16) / 17)
                                                : (bid - N_GEMM);
        if (fillIdx < 8192) {
            // optimal_routes: v[..., j] = -(float)j/1024 exactly
            float4* out4 = (float4*)(out + OFF_ROUTES);
            long long base = fillIdx * 2048;
            const float r = 1.0f / 1024.0f;
            #pragma unroll
            for (int it = 0; it < 8; it++) {
                long long q = base + it * 256 + tid;
                int c = (int)(q & 255) << 2;
                float4 v;
                v.x = -(float)(c + 0) * r;
                v.y = -(float)(c + 1) * r;
                v.z = -(float)(c + 2) * r;
                v.w = -(float)(c + 3) * r;
                __stcs(&out4[q], v);
            }
        } else {
            int i4 = (int)(fillIdx - 8192) * 256 + tid;
            const float r = 1.0f / 1024.0f;
            ((float4*)(out + OFF_ROUTING))[i4] = make_float4(r, r, r, r);
            ((float4*)(out + OFF_TW))[i4] = ((const float4*)tw_in)[i4];
        }
        return;
    }

    // ================ GEMM tile: 128 rows x 64 patterns, K=256 ================
    int gemmIdx = bid / 17;
    long long rowBase = (long long)gemmIdx * 128;
    const float* A = states + rowBase * DD;

    float* sNorm = smem;                     // [64]
    float* sInv  = smem + 64;                // [128]
    float* sA    = smem + SA_OFF;            // [128][68]
    uint2* sB2   = (uint2*)(smem + SB2_OFF); // [64][68] {hi,lo}

    // ---- pattern inverse norms (temp partials in sA region) ----
    {
        float* tmp = sA;                     // 256 floats
        int p = tid >> 2, q = tid & 3;
        const float4* pv = (const float4*)(patterns + p * DD + q * 64);
        float ss = 0.0f;
        #pragma unroll
        for (int i = 0; i < 16; i++) {
            float4 v = pv[i];
            ss = fmaf(v.x, v.x, fmaf(v.y, v.y, fmaf(v.z, v.z, fmaf(v.w, v.w, ss))));
        }
        tmp[tid] = ss;
        __syncthreads();
        if (tid < 64) {
            float s = tmp[tid * 4] + tmp[tid * 4 + 1] + tmp[tid * 4 + 2] + tmp[tid * 4 + 3];
            sNorm[tid] = 1.0f / fmaxf(sqrtf(s), 1e-12f);
        }
    }

    int w    = tid >> 5;
    int lane = tid & 31;
    int g    = lane >> 2;    // group id 0..7
    int tig  = lane & 3;     // thread in group

    float acc[8][4];
    #pragma unroll
    for (int nb = 0; nb < 8; nb++)
        #pragma unroll
        for (int i = 0; i < 4; i++) acc[nb][i] = 0.0f;

    const float* aRow0 = sA + (w * 16 + g) * PITCH;
    const float* aRow8 = aRow0 + 8 * PITCH;

    for (int c = 0; c < 4; c++) {       // 4 chunks of K=64
        __syncthreads();
        // stage A chunk: 128 rows x 64 k fp32, 8 float4 per thread
        #pragma unroll
        for (int j = 0; j < 8; j++) {
            int i = tid + j * 256;
            int row = i >> 4, seg = i & 15;
            float4 v = *(const float4*)&A[(long long)row * DD + c * 64 + seg * 4];
            *(float4*)&sA[row * PITCH + seg * 4] = v;
        }
        // stage B chunk: 64 patterns x 64 k, normalized + tf32-split ONCE.
        // thread -> pattern p = tid>>2, 16 consecutive k at (tid&3)*16
        {
            int p   = tid >> 2;
            int kb  = (tid & 3) * 16;
            float inv = sNorm[p];
            #pragma unroll
            for (int j = 0; j < 4; j++) {
                int k = kb + j * 4;
                float4 v = *(const float4*)&patterns[p * DD + c * 64 + k];
                unsigned h0, l0, h1, l1, h2, l2, h3, l3;
                split_tf32(v.x * inv, h0, l0);
                split_tf32(v.y * inv, h1, l1);
                split_tf32(v.z * inv, h2, l2);
                split_tf32(v.w * inv, h3, l3);
                uint2* dst = &sB2[p * PITCH_B2 + k];
                *(uint4*)(dst + 0) = make_uint4(h0, l0, h1, l1);
                *(uint4*)(dst + 2) = make_uint4(h2, l2, h3, l3);
            }
        }
        __syncthreads();

        #pragma unroll
        for (int ks = 0; ks < 8; ks++) {
            int k0 = ks * 8;
            unsigned ah0, ah1, ah2, ah3, al0, al1, al2, al3;
            split_tf32(aRow0[k0 + tig],     ah0, al0);
            split_tf32(aRow8[k0 + tig],     ah1, al1);
            split_tf32(aRow0[k0 + tig + 4], ah2, al2);
            split_tf32(aRow8[k0 + tig + 4], ah3, al3);
            #pragma unroll
            for (int nb = 0; nb < 8; nb++) {
                const uint2* bp = &sB2[(nb * 8 + g) * PITCH_B2 + k0 + tig];
                uint2 b0 = bp[0];          // {hi, lo} at k0+tig
                uint2 b1 = bp[4];          // {hi, lo} at k0+tig+4
                mma_tf32(acc[nb], ah0, ah1, ah2, ah3, b0.x, b1.x);
                mma_tf32(acc[nb], ah0, ah1, ah2, ah3, b0.y, b1.y);
                mma_tf32(acc[nb], al0, al1, al2, al3, b0.x, b1.x);
            }
        }
    }
    __syncthreads();

    // ================ epilogue: softmax over 64 patterns per row ================
    float* sS = sA;   // overlay [128][66]
    {
        int r0 = w * 16 + g;
        #pragma unroll
        for (int nb = 0; nb < 8; nb++) {
            int col = nb * 8 + 2 * tig;
            *(float2*)&sS[r0 * 66 + col]       = make_float2(acc[nb][0], acc[nb][1]);
            *(float2*)&sS[(r0 + 8) * 66 + col] = make_float2(acc[nb][2], acc[nb][3]);
        }
    }
    __syncthreads();

    if (tid < 128) {
        float* rowp = &sS[tid * 66];
        float mx = -1e30f;
        #pragma unroll
        for (int p = 0; p < PP; p++) mx = fmaxf(mx, rowp[p]);
        mx *= TINV;
        float sum = 0.0f;
        #pragma unroll
        for (int p = 0; p < PP; p++) {
            float e = __expf(rowp[p] * TINV - mx);
            rowp[p] = e;
            sum += e;
        }
        sInv[tid] = 1.0f / sum;
    }
    __syncthreads();

    // coalesced streaming store of the 128x64 tile
    float* O = out + OFF_PS + rowBase * PP;
    for (int i = tid; i < 128 * PP / 4; i += 256) {
        int row = i >> 4, pq = (i & 15) << 2;
        float inv = sInv[row];
        float4 v = make_float4(sS[row * 66 + pq + 0] * inv,
                               sS[row * 66 + pq + 1] * inv,
                               sS[row * 66 + pq + 2] * inv,
                               sS[row * 66 + pq + 3] * inv);
        __stcs((float4*)&O[row * PP + pq], v);
    }
}

extern "C" void kernel_launch(void* const* d_in, const int* in_sizes, int n_in,
                              void* d_out, int out_size) {
    const float* states   = (const float*)d_in[0];  // (4,16,1024,256)
    const float* patterns = (const float*)d_in[1];  // (64,256)
    const float* tw       = (const float*)d_in[2];  // (16,64,64)
    float* out = (float*)d_out;

    cudaFuncSetAttribute(fused_kernel,
                         cudaFuncAttributeMaxDynamicSharedMemorySize,
                         SMEM_BYTES);

    fused_kernel<<<GRID_TOTAL, 256, SMEM_BYTES>>>(states, patterns, tw, out);
}

// round 10
// speedup vs baseline: 1.0179x; 1.0179x over previous
#include <cuda_runtime.h>
#include <math.h>
#include <stdint.h>

// Problem constants
#define DD 256
#define PP 64
#define TINV 10.0f

// Output offsets (floats): routing(65536) | routes(67108864) | tw(65536) | ps(4194304)
#define OFF_ROUTING 0LL
#define OFF_ROUTES  65536LL
#define OFF_TW      67174400LL
#define OFF_PS      67239936LL

#define N_GEMM 512          // 65536 rows / 128 rows per tile
#define GRID_TOTAL 8768

// smem (floats): [0,64) normInv | [64,192) sInv | [256,+128*68) sA | then sB 64*68
// epilogue overlay: sS[128][66] at sA (8448 <= 13056 floats of sA+sB)
#define PITCH 68
#define SA_OFF 256
#define SB_OFF (SA_OFF + 128 * PITCH)
#define SMEM_FLOATS (SB_OFF + 64 * PITCH)     // 13312
#define SMEM_BYTES (SMEM_FLOATS * 4)          // 53248 B -> 4 CTAs/SM

// ---- tf32 helpers ----
__device__ __forceinline__ unsigned f2tf(float x) {
    unsigned r;
    asm("cvt.rna.tf32.f32 %0, %1;" : "=r"(r) : "f"(x));
    return r;
}
__device__ __forceinline__ void split_tf32(float x, unsigned& hi, unsigned& lo) {
    hi = f2tf(x);
    lo = f2tf(x - __uint_as_float(hi));
}
__device__ __forceinline__ void mma_tf32(float* c,
                                         unsigned a0, unsigned a1, unsigned a2, unsigned a3,
                                         unsigned b0, unsigned b1) {
    asm volatile(
        "mma.sync.aligned.m16n8k8.row.col.f32.tf32.tf32.f32 "
        "{%0,%1,%2,%3}, {%4,%5,%6,%7}, {%8,%9}, {%0,%1,%2,%3};"
        : "+f"(c[0]), "+f"(c[1]), "+f"(c[2]), "+f"(c[3])
        : "r"(a0), "r"(a1), "r"(a2), "r"(a3), "r"(b0), "r"(b1));
}

// ---------------------------------------------------------------------------
// Single fused kernel: TF32-mma GEMM+softmax tiles interleaved with fill CTAs.
// ---------------------------------------------------------------------------
__global__ __launch_bounds__(256, 4)
void fused_kernel(const float* __restrict__ states,
                  const float* __restrict__ patterns,
                  const float* __restrict__ tw_in,
                  float* __restrict__ out) {
    extern __shared__ float smem[];
    int bid = blockIdx.x;
    int tid = threadIdx.x;

    bool isGemm = (bid < 17 * N_GEMM) && (bid % 17 == 0);

    if (!isGemm) {
        long long fillIdx = (bid < 17 * N_GEMM) ? (bid - (bid + 16) / 17)
                                                : (bid - N_GEMM);
        if (fillIdx < 8192) {
            // optimal_routes: v[..., j] = -(float)j/1024 exactly.
            // q & 255 == tid for every iteration -> value is loop-invariant.
            const float r = 1.0f / 1024.0f;
            int c = tid << 2;
            float4 v;
            v.x = -(float)(c + 0) * r;
            v.y = -(float)(c + 1) * r;
            v.z = -(float)(c + 2) * r;
            v.w = -(float)(c + 3) * r;
            float4* p = (float4*)(out + OFF_ROUTES) + fillIdx * 2048 + tid;
            #pragma unroll
            for (int it = 0; it < 8; it++)
                __stcs(p + it * 256, v);
        } else {
            int i4 = (int)(fillIdx - 8192) * 256 + tid;
            const float r = 1.0f / 1024.0f;
            ((float4*)(out + OFF_ROUTING))[i4] = make_float4(r, r, r, r);
            ((float4*)(out + OFF_TW))[i4] = ((const float4*)tw_in)[i4];
        }
        return;
    }

    // ================ GEMM tile: 128 rows x 64 patterns, K=256 ================
    int gemmIdx = bid / 17;
    long long rowBase = (long long)gemmIdx * 128;
    const float* A = states + rowBase * DD;

    float* sNorm = smem;            // [64]
    float* sInv  = smem + 64;       // [128]
    float* sA    = smem + SA_OFF;   // [128][68]
    float* sB    = smem + SB_OFF;   // [64][68]

    // ---- pattern inverse norms (temp partials in sA region) ----
    {
        float* tmp = sA;                       // 256 floats
        int p = tid >> 2, q = tid & 3;
        const float4* pv = (const float4*)(patterns + p * DD + q * 64);
        float ss = 0.0f;
        #pragma unroll
        for (int i = 0; i < 16; i++) {
            float4 v = pv[i];
            ss = fmaf(v.x, v.x, fmaf(v.y, v.y, fmaf(v.z, v.z, fmaf(v.w, v.w, ss))));
        }
        tmp[tid] = ss;
        __syncthreads();
        if (tid < 64) {
            float s = tmp[tid * 4] + tmp[tid * 4 + 1] + tmp[tid * 4 + 2] + tmp[tid * 4 + 3];
            sNorm[tid] = 1.0f / fmaxf(sqrtf(s), 1e-12f);
        }
    }

    int w    = tid >> 5;
    int lane = tid & 31;
    int g    = lane >> 2;    // group id 0..7
    int tig  = lane & 3;     // thread in group

    float acc[8][4];
    #pragma unroll
    for (int nb = 0; nb < 8; nb++)
        #pragma unroll
        for (int i = 0; i < 4; i++) acc[nb][i] = 0.0f;

    const float* aRow0 = sA + (w * 16 + g) * PITCH;
    const float* aRow8 = aRow0 + 8 * PITCH;

    for (int c = 0; c < 4; c++) {       // 4 chunks of K=64
        __syncthreads();
        // stage A chunk: 128 rows x 64 k, 8 float4 per thread
        #pragma unroll
        for (int j = 0; j < 8; j++) {
            int i = tid + j * 256;
            int row = i >> 4, seg = i & 15;
            float4 v = *(const float4*)&A[(long long)row * DD + c * 64 + seg * 4];
            *(float4*)&sA[row * PITCH + seg * 4] = v;
        }
        // stage B chunk: 64 patterns x 64 k, normalized, 4 float4 per thread
        #pragma unroll
        for (int j = 0; j < 4; j++) {
            int i = tid + j * 256;
            int p = i >> 4, seg = i & 15;
            float inv = sNorm[p];
            float4 v = *(const float4*)&patterns[p * DD + c * 64 + seg * 4];
            v.x *= inv; v.y *= inv; v.z *= inv; v.w *= inv;
            *(float4*)&sB[p * PITCH + seg * 4] = v;
        }
        __syncthreads();

        #pragma unroll
        for (int ks = 0; ks < 8; ks++) {
            int k0 = ks * 8;
            unsigned ah0, ah1, ah2, ah3, al0, al1, al2, al3;
            split_tf32(aRow0[k0 + tig],     ah0, al0);
            split_tf32(aRow8[k0 + tig],     ah1, al1);
            split_tf32(aRow0[k0 + tig + 4], ah2, al2);
            split_tf32(aRow8[k0 + tig + 4], ah3, al3);
            #pragma unroll
            for (int nb = 0; nb < 8; nb++) {
                const float* bp = sB + (nb * 8 + g) * PITCH + k0 + tig;
                unsigned bh0, bl0, bh1, bl1;
                split_tf32(bp[0], bh0, bl0);
                split_tf32(bp[4], bh1, bl1);
                mma_tf32(acc[nb], ah0, ah1, ah2, ah3, bh0, bh1);
                mma_tf32(acc[nb], ah0, ah1, ah2, ah3, bl0, bl1);
                mma_tf32(acc[nb], al0, al1, al2, al3, bh0, bh1);
            }
        }
    }
    __syncthreads();

    // ================ epilogue: softmax over 64 patterns per row ================
    float* sS = sA;   // overlay [128][66]
    {
        int r0 = w * 16 + g;
        #pragma unroll
        for (int nb = 0; nb < 8; nb++) {
            int col = nb * 8 + 2 * tig;
            *(float2*)&sS[r0 * 66 + col]       = make_float2(acc[nb][0], acc[nb][1]);
            *(float2*)&sS[(r0 + 8) * 66 + col] = make_float2(acc[nb][2], acc[nb][3]);
        }
    }
    __syncthreads();

    if (tid < 128) {
        float* rowp = &sS[tid * 66];
        float mx = -1e30f;
        #pragma unroll
        for (int p = 0; p < PP; p++) mx = fmaxf(mx, rowp[p]);
        mx *= TINV;
        float sum = 0.0f;
        #pragma unroll
        for (int p = 0; p < PP; p++) {
            float e = __expf(rowp[p] * TINV - mx);
            rowp[p] = e;
            sum += e;
        }
        sInv[tid] = 1.0f / sum;
    }
    __syncthreads();

    // coalesced streaming store of the 128x64 tile
    float* O = out + OFF_PS + rowBase * PP;
    for (int i = tid; i < 128 * PP / 4; i += 256) {
        int row = i >> 4, pq = (i & 15) << 2;
        float inv = sInv[row];
        float4 v = make_float4(sS[row * 66 + pq + 0] * inv,
                               sS[row * 66 + pq + 1] * inv,
                               sS[row * 66 + pq + 2] * inv,
                               sS[row * 66 + pq + 3] * inv);
        __stcs((float4*)&O[row * PP + pq], v);
    }
}

extern "C" void kernel_launch(void* const* d_in, const int* in_sizes, int n_in,
                              void* d_out, int out_size) {
    const float* states   = (const float*)d_in[0];  // (4,16,1024,256)
    const float* patterns = (const float*)d_in[1];  // (64,256)
    const float* tw       = (const float*)d_in[2];  // (16,64,64)
    float* out = (float*)d_out;

    cudaFuncSetAttribute(fused_kernel,
                         cudaFuncAttributeMaxDynamicSharedMemorySize,
                         SMEM_BYTES);

    fused_kernel<<<GRID_TOTAL, 256, SMEM_BYTES>>>(states, patterns, tw, out);
}

// round 11
// speedup vs baseline: 1.0653x; 1.0466x over previous
#include <cuda_runtime.h>
#include <math.h>
#include <stdint.h>

// Problem constants
#define DD 256
#define PP 64
#define TINV 10.0f

// Output offsets (floats): routing(65536) | routes(67108864) | tw(65536) | ps(4194304)
#define OFF_ROUTING 0LL
#define OFF_ROUTES  65536LL
#define OFF_TW      67174400LL
#define OFF_PS      67239936LL

#define N_GEMM 512          // 65536 rows / 128 rows per tile
#define GRID_TOTAL 8768

// smem (floats): [0,64) normInv | [64,192) sInv | [256, 256+128*76) sA | then sB 64*76
// epilogue overlay: sS[128][66] at sA (8448 <= 9728 floats)
#define PITCH 76
#define SA_OFF 256
#define SB_OFF (SA_OFF + 128 * PITCH)
#define SMEM_FLOATS (SB_OFF + 64 * PITCH)
#define SMEM_BYTES (SMEM_FLOATS * 4)      // 59392 B -> 3 CTAs/SM

// ---- tf32 helpers ----
__device__ __forceinline__ unsigned f2tf(float x) {
    unsigned r;
    asm("cvt.rna.tf32.f32 %0, %1;" : "=r"(r) : "f"(x));
    return r;
}
__device__ __forceinline__ void split_tf32(float x, unsigned& hi, unsigned& lo) {
    hi = f2tf(x);
    lo = f2tf(x - __uint_as_float(hi));
}
__device__ __forceinline__ void mma_tf32(float* c,
                                         unsigned a0, unsigned a1, unsigned a2, unsigned a3,
                                         unsigned b0, unsigned b1) {
    asm volatile(
        "mma.sync.aligned.m16n8k8.row.col.f32.tf32.tf32.f32 "
        "{%0,%1,%2,%3}, {%4,%5,%6,%7}, {%8,%9}, {%0,%1,%2,%3};"
        : "+f"(c[0]), "+f"(c[1]), "+f"(c[2]), "+f"(c[3])
        : "r"(a0), "r"(a1), "r"(a2), "r"(a3), "r"(b0), "r"(b1));
}

// ---------------------------------------------------------------------------
// Single fused kernel: TF32-mma GEMM+softmax tiles interleaved with fill CTAs.
// ---------------------------------------------------------------------------
__global__ __launch_bounds__(256, 3)
void fused_kernel(const float* __restrict__ states,
                  const float* __restrict__ patterns,
                  const float* __restrict__ tw_in,
                  float* __restrict__ out) {
    extern __shared__ float smem[];
    int bid = blockIdx.x;
    int tid = threadIdx.x;

    bool isGemm = (bid < 17 * N_GEMM) && (bid % 17 == 0);

    if (!isGemm) {
        long long fillIdx = (bid < 17 * N_GEMM) ? (bid - (bid + 16) / 17)
                                                : (bid - N_GEMM);
        if (fillIdx < 8192) {
            // optimal_routes: v[..., j] = -(float)j/1024 exactly.
            // Column index == 4*tid for every store of this thread -> hoist.
            const float r = 1.0f / 1024.0f;
            int c = tid << 2;
            float4 v;
            v.x = -(float)(c + 0) * r;
            v.y = -(float)(c + 1) * r;
            v.z = -(float)(c + 2) * r;
            v.w = -(float)(c + 3) * r;
            float4* p = (float4*)(out + OFF_ROUTES) + fillIdx * 2048 + tid;
            #pragma unroll
            for (int it = 0; it < 8; it++)
                __stcs(p + it * 256, v);
        } else {
            int i4 = (int)(fillIdx - 8192) * 256 + tid;
            const float r = 1.0f / 1024.0f;
            ((float4*)(out + OFF_ROUTING))[i4] = make_float4(r, r, r, r);
            ((float4*)(out + OFF_TW))[i4] = ((const float4*)tw_in)[i4];
        }
        return;
    }

    // ================ GEMM tile: 128 rows x 64 patterns, K=256 ================
    int gemmIdx = bid / 17;
    long long rowBase = (long long)gemmIdx * 128;
    const float* A = states + rowBase * DD;

    float* sNorm = smem;            // [64]
    float* sInv  = smem + 64;       // [128]
    float* sA    = smem + SA_OFF;   // [128][76]
    float* sB    = smem + SB_OFF;   // [64][76]

    // ---- pattern inverse norms (temp partials in sA region) ----
    {
        float* tmp = sA;                       // 256 floats
        int p = tid >> 2, q = tid & 3;
        const float4* pv = (const float4*)(patterns + p * DD + q * 64);
        float ss = 0.0f;
        #pragma unroll
        for (int i = 0; i < 16; i++) {
            float4 v = pv[i];
            ss = fmaf(v.x, v.x, fmaf(v.y, v.y, fmaf(v.z, v.z, fmaf(v.w, v.w, ss))));
        }
        tmp[tid] = ss;
        __syncthreads();
        if (tid < 64) {
            float s = tmp[tid * 4] + tmp[tid * 4 + 1] + tmp[tid * 4 + 2] + tmp[tid * 4 + 3];
            sNorm[tid] = 1.0f / fmaxf(sqrtf(s), 1e-12f);
        }
    }

    int w    = tid >> 5;
    int lane = tid & 31;
    int g    = lane >> 2;    // group id 0..7
    int tig  = lane & 3;     // thread in group

    float acc[8][4];
    #pragma unroll
    for (int nb = 0; nb < 8; nb++)
        #pragma unroll
        for (int i = 0; i < 4; i++) acc[nb][i] = 0.0f;

    const float* aRow0 = sA + (w * 16 + g) * PITCH;
    const float* aRow8 = aRow0 + 8 * PITCH;

    for (int c = 0; c < 4; c++) {       // 4 chunks of K=64
        __syncthreads();
        // stage A chunk: 128 rows x 64 k, 8 float4 per thread
        #pragma unroll
        for (int j = 0; j < 8; j++) {
            int i = tid + j * 256;
            int row = i >> 4, seg = i & 15;
            float4 v = *(const float4*)&A[(long long)row * DD + c * 64 + seg * 4];
            *(float4*)&sA[row * PITCH + seg * 4] = v;
        }
        // stage B chunk: 64 patterns x 64 k, normalized, 4 float4 per thread
        #pragma unroll
        for (int j = 0; j < 4; j++) {
            int i = tid + j * 256;
            int p = i >> 4, seg = i & 15;
            float inv = sNorm[p];
            float4 v = *(const float4*)&patterns[p * DD + c * 64 + seg * 4];
            v.x *= inv; v.y *= inv; v.z *= inv; v.w *= inv;
            *(float4*)&sB[p * PITCH + seg * 4] = v;
        }
        __syncthreads();

        #pragma unroll
        for (int ks = 0; ks < 8; ks++) {
            int k0 = ks * 8;
            unsigned ah0, ah1, ah2, ah3, al0, al1, al2, al3;
            split_tf32(aRow0[k0 + tig],     ah0, al0);
            split_tf32(aRow8[k0 + tig],     ah1, al1);
            split_tf32(aRow0[k0 + tig + 4], ah2, al2);
            split_tf32(aRow8[k0 + tig + 4], ah3, al3);
            #pragma unroll
            for (int nb = 0; nb < 8; nb++) {
                const float* bp = sB + (nb * 8 + g) * PITCH + k0 + tig;
                unsigned bh0, bl0, bh1, bl1;
                split_tf32(bp[0], bh0, bl0);
                split_tf32(bp[4], bh1, bl1);
                mma_tf32(acc[nb], ah0, ah1, ah2, ah3, bh0, bh1);
                mma_tf32(acc[nb], ah0, ah1, ah2, ah3, bl0, bl1);
                mma_tf32(acc[nb], al0, al1, al2, al3, bh0, bh1);
            }
        }
    }
    __syncthreads();

    // ================ epilogue: softmax over 64 patterns per row ================
    float* sS = sA;   // overlay [128][66]
    {
        int r0 = w * 16 + g;
        #pragma unroll
        for (int nb = 0; nb < 8; nb++) {
            int col = nb * 8 + 2 * tig;
            *(float2*)&sS[r0 * 66 + col]       = make_float2(acc[nb][0], acc[nb][1]);
            *(float2*)&sS[(r0 + 8) * 66 + col] = make_float2(acc[nb][2], acc[nb][3]);
        }
    }
    __syncthreads();

    // 2 threads per row: thread (row, half) handles 32 patterns; shfl-combine.
    {
        int row  = tid >> 1;
        int half = tid & 1;
        float* rowp = &sS[row * 66 + half * 32];
        float mx = -1e30f;
        #pragma unroll
        for (int p = 0; p < 32; p++) mx = fmaxf(mx, rowp[p]);
        mx = fmaxf(mx, __shfl_xor_sync(0xFFFFFFFFu, mx, 1));
        mx *= TINV;
        float sum = 0.0f;
        #pragma unroll
        for (int p = 0; p < 32; p++) {
            float e = __expf(rowp[p] * TINV - mx);
            rowp[p] = e;
            sum += e;
        }
        sum += __shfl_xor_sync(0xFFFFFFFFu, sum, 1);
        if (half == 0) sInv[row] = 1.0f / sum;
    }
    __syncthreads();

    // coalesced streaming store of the 128x64 tile
    float* O = out + OFF_PS + rowBase * PP;
    for (int i = tid; i < 128 * PP / 4; i += 256) {
        int row = i >> 4, pq = (i & 15) << 2;
        float inv = sInv[row];
        float4 v = make_float4(sS[row * 66 + pq + 0] * inv,
                               sS[row * 66 + pq + 1] * inv,
                               sS[row * 66 + pq + 2] * inv,
                               sS[row * 66 + pq + 3] * inv);
        __stcs((float4*)&O[row * PP + pq], v);
    }
}

extern "C" void kernel_launch(void* const* d_in, const int* in_sizes, int n_in,
                              void* d_out, int out_size) {
    const float* states   = (const float*)d_in[0];  // (4,16,1024,256)
    const float* patterns = (const float*)d_in[1];  // (64,256)
    const float* tw       = (const float*)d_in[2];  // (16,64,64)
    float* out = (float*)d_out;

    cudaFuncSetAttribute(fused_kernel,
                         cudaFuncAttributeMaxDynamicSharedMemorySize,
                         SMEM_BYTES);

    fused_kernel<<<GRID_TOTAL, 256, SMEM_BYTES>>>(states, patterns, tw, out);
}

// round 12
// speedup vs baseline: 1.1203x; 1.0516x over previous
#include <cuda_runtime.h>
#include <math.h>
#include <stdint.h>

// Problem constants
#define DD 256
#define PP 64
#define TINV 10.0f

// Output offsets (floats): routing(65536) | routes(67108864) | tw(65536) | ps(4194304)
#define OFF_ROUTING 0LL
#define OFF_ROUTES  65536LL
#define OFF_TW      67174400LL
#define OFF_PS      67239936LL

#define GRID_TOTAL 1024     // uniform CTAs: 64-row GEMM tile + 1/1024 of all fills

// smem (floats): [0,64) normInv | [64,128) sInv | [256,+64*76) sA | then sB 64*76
// epilogue overlay: sS[64][66] at sA (4224 <= 9728)
#define PITCH 76
#define SA_OFF 256
#define SB_OFF (SA_OFF + 64 * PITCH)
#define SMEM_FLOATS (SB_OFF + 64 * PITCH)
#define SMEM_BYTES (SMEM_FLOATS * 4)      // 39936 B

// ---- tf32 helpers ----
__device__ __forceinline__ unsigned f2tf(float x) {
    unsigned r;
    asm("cvt.rna.tf32.f32 %0, %1;" : "=r"(r) : "f"(x));
    return r;
}
__device__ __forceinline__ void split_tf32(float x, unsigned& hi, unsigned& lo) {
    hi = f2tf(x);
    lo = f2tf(x - __uint_as_float(hi));
}
__device__ __forceinline__ void mma_tf32(float* c,
                                         unsigned a0, unsigned a1, unsigned a2, unsigned a3,
                                         unsigned b0, unsigned b1) {
    asm volatile(
        "mma.sync.aligned.m16n8k8.row.col.f32.tf32.tf32.f32 "
        "{%0,%1,%2,%3}, {%4,%5,%6,%7}, {%8,%9}, {%0,%1,%2,%3};"
        : "+f"(c[0]), "+f"(c[1]), "+f"(c[2]), "+f"(c[3])
        : "r"(a0), "r"(a1), "r"(a2), "r"(a3), "r"(b0), "r"(b1));
}

// ---------------------------------------------------------------------------
// Uniform fused kernel: every CTA = 64-row GEMM+softmax tile + fill share,
// route stores interleaved into the K-chunk loop for continuous R/W mix.
// ---------------------------------------------------------------------------
__global__ __launch_bounds__(256, 3)
void fused_kernel(const float* __restrict__ states,
                  const float* __restrict__ patterns,
                  const float* __restrict__ tw_in,
                  float* __restrict__ out) {
    extern __shared__ float smem[];
    int bid = blockIdx.x;
    int tid = threadIdx.x;

    long long rowBase = (long long)bid * 64;
    const float* A = states + rowBase * DD;

    float* sNorm = smem;            // [64]
    float* sInv  = smem + 64;       // [64]
    float* sA    = smem + SA_OFF;   // [64][76]
    float* sB    = smem + SB_OFF;   // [64][76]

    // ---- hoisted route-fill constants: this CTA covers R[bid*16384 .. +16384) ----
    // column of float4 index q is (q & 255); our stores use q = base + j*256 + tid,
    // so column == tid for every store -> value loop-invariant.
    float4 rv;
    {
        const float r = 1.0f / 1024.0f;
        int c = tid << 2;
        rv.x = -(float)(c + 0) * r;
        rv.y = -(float)(c + 1) * r;
        rv.z = -(float)(c + 2) * r;
        rv.w = -(float)(c + 3) * r;
    }
    float4* routes4 = (float4*)(out + OFF_ROUTES) + (long long)bid * 16384 + tid;

    // ---- small fills: 16 float4 of routing + 16 of tw per CTA ----
    if (tid < 16) {
        const float r = 1.0f / 1024.0f;
        ((float4*)(out + OFF_ROUTING))[bid * 16 + tid] = make_float4(r, r, r, r);
    } else if (tid < 32) {
        int i4 = bid * 16 + (tid - 16);
        ((float4*)(out + OFF_TW))[i4] = ((const float4*)tw_in)[i4];
    }

    // ---- pattern inverse norms (temp partials in sA region) ----
    {
        float* tmp = sA;                       // 256 floats
        int p = tid >> 2, q = tid & 3;
        const float4* pv = (const float4*)(patterns + p * DD + q * 64);
        float ss = 0.0f;
        #pragma unroll
        for (int i = 0; i < 16; i++) {
            float4 v = pv[i];
            ss = fmaf(v.x, v.x, fmaf(v.y, v.y, fmaf(v.z, v.z, fmaf(v.w, v.w, ss))));
        }
        tmp[tid] = ss;
        __syncthreads();
        if (tid < 64) {
            float s = tmp[tid * 4] + tmp[tid * 4 + 1] + tmp[tid * 4 + 2] + tmp[tid * 4 + 3];
            sNorm[tid] = 1.0f / fmaxf(sqrtf(s), 1e-12f);
        }
    }

    int w    = tid >> 5;     // warp 0..7
    int lane = tid & 31;
    int g    = lane >> 2;    // group id 0..7
    int tig  = lane & 3;     // thread in group
    int wr   = w & 3;        // row-block of warp   (rows wr*16 .. wr*16+15)
    int wc   = w >> 2;       // col-half of warp    (cols wc*32 .. wc*32+31)

    float acc[4][4];
    #pragma unroll
    for (int nb = 0; nb < 4; nb++)
        #pragma unroll
        for (int i = 0; i < 4; i++) acc[nb][i] = 0.0f;

    const float* aRow0 = sA + (wr * 16 + g) * PITCH;
    const float* aRow8 = aRow0 + 8 * PITCH;

    for (int c = 0; c < 4; c++) {       // 4 chunks of K=64
        __syncthreads();
        // stage A chunk: 64 rows x 64 k, 4 float4 per thread
        #pragma unroll
        for (int j = 0; j < 4; j++) {
            int i = tid + j * 256;
            int row = i >> 4, seg = i & 15;
            float4 v = *(const float4*)&A[(long long)row * DD + c * 64 + seg * 4];
            *(float4*)&sA[row * PITCH + seg * 4] = v;
        }
        // stage B chunk: 64 patterns x 64 k, normalized, 4 float4 per thread
        #pragma unroll
        for (int j = 0; j < 4; j++) {
            int i = tid + j * 256;
            int p = i >> 4, seg = i & 15;
            float inv = sNorm[p];
            float4 v = *(const float4*)&patterns[p * DD + c * 64 + seg * 4];
            v.x *= inv; v.y *= inv; v.z *= inv; v.w *= inv;
            *(float4*)&sB[p * PITCH + seg * 4] = v;
        }
        __syncthreads();

        // interleaved route-fill: 16 independent streaming stores per thread
        #pragma unroll
        for (int j = 0; j < 16; j++)
            __stcs(routes4 + (c * 16 + j) * 256, rv);

        #pragma unroll
        for (int ks = 0; ks < 8; ks++) {
            int k0 = ks * 8;
            unsigned ah0, ah1, ah2, ah3, al0, al1, al2, al3;
            split_tf32(aRow0[k0 + tig],     ah0, al0);
            split_tf32(aRow8[k0 + tig],     ah1, al1);
            split_tf32(aRow0[k0 + tig + 4], ah2, al2);
            split_tf32(aRow8[k0 + tig + 4], ah3, al3);
            #pragma unroll
            for (int nb = 0; nb < 4; nb++) {
                const float* bp = sB + (wc * 32 + nb * 8 + g) * PITCH + k0 + tig;
                unsigned bh0, bl0, bh1, bl1;
                split_tf32(bp[0], bh0, bl0);
                split_tf32(bp[4], bh1, bl1);
                mma_tf32(acc[nb], ah0, ah1, ah2, ah3, bh0, bh1);
                mma_tf32(acc[nb], ah0, ah1, ah2, ah3, bl0, bl1);
                mma_tf32(acc[nb], al0, al1, al2, al3, bh0, bh1);
            }
        }
    }
    __syncthreads();

    // ================ epilogue: softmax over 64 patterns per row ================
    float* sS = sA;   // overlay [64][66]
    {
        int r0 = wr * 16 + g;
        #pragma unroll
        for (int nb = 0; nb < 4; nb++) {
            int col = wc * 32 + nb * 8 + 2 * tig;
            *(float2*)&sS[r0 * 66 + col]       = make_float2(acc[nb][0], acc[nb][1]);
            *(float2*)&sS[(r0 + 8) * 66 + col] = make_float2(acc[nb][2], acc[nb][3]);
        }
    }
    __syncthreads();

    // 4 threads per row: thread (row, q) handles 16 patterns; shfl-combine.
    {
        int row = tid >> 2;
        int q   = tid & 3;
        float* rowp = &sS[row * 66 + q * 16];
        float mx = -1e30f;
        #pragma unroll
        for (int p = 0; p < 16; p++) mx = fmaxf(mx, rowp[p]);
        mx = fmaxf(mx, __shfl_xor_sync(0xFFFFFFFFu, mx, 1));
        mx = fmaxf(mx, __shfl_xor_sync(0xFFFFFFFFu, mx, 2));
        mx *= TINV;
        float sum = 0.0f;
        #pragma unroll
        for (int p = 0; p < 16; p++) {
            float e = __expf(rowp[p] * TINV - mx);
            rowp[p] = e;
            sum += e;
        }
        sum += __shfl_xor_sync(0xFFFFFFFFu, sum, 1);
        sum += __shfl_xor_sync(0xFFFFFFFFu, sum, 2);
        if (q == 0) sInv[row] = 1.0f / sum;
    }
    __syncthreads();

    // coalesced streaming store of the 64x64 tile
    float* O = out + OFF_PS + rowBase * PP;
    #pragma unroll
    for (int j = 0; j < 4; j++) {
        int i = tid + j * 256;
        int row = i >> 4, pq = (i & 15) << 2;
        float inv = sInv[row];
        float4 v = make_float4(sS[row * 66 + pq + 0] * inv,
                               sS[row * 66 + pq + 1] * inv,
                               sS[row * 66 + pq + 2] * inv,
                               sS[row * 66 + pq + 3] * inv);
        __stcs((float4*)&O[row * PP + pq], v);
    }
}

extern "C" void kernel_launch(void* const* d_in, const int* in_sizes, int n_in,
                              void* d_out, int out_size) {
    const float* states   = (const float*)d_in[0];  // (4,16,1024,256)
    const float* patterns = (const float*)d_in[1];  // (64,256)
    const float* tw       = (const float*)d_in[2];  // (16,64,64)
    float* out = (float*)d_out;

    cudaFuncSetAttribute(fused_kernel,
                         cudaFuncAttributeMaxDynamicSharedMemorySize,
                         SMEM_BYTES);

    fused_kernel<<<GRID_TOTAL, 256, SMEM_BYTES>>>(states, patterns, tw, out);
}

// round 13
// speedup vs baseline: 1.2607x; 1.1254x over previous
#include <cuda_runtime.h>
#include <math.h>
#include <stdint.h>

// Problem constants
#define DD 256
#define PP 64
#define TINV 10.0f

// Output offsets (floats): routing(65536) | routes(67108864) | tw(65536) | ps(4194304)
#define OFF_ROUTING 0LL
#define OFF_ROUTES  65536LL
#define OFF_TW      67174400LL
#define OFF_PS      67239936LL

#define GRID_TOTAL 1024     // uniform CTAs: 64-row GEMM tile + 1/1024 of all fills

// smem (floats):
//  [0,64) sNorm | [64,128) sInv | [128,384) tmp partials
//  [384, 384+2*64*68)  sA double buffer (raw fp32)
//  [9088, 9088+2*64*68) sB double buffer (raw fp32)
// epilogue overlay: sS[64][66] (4224) fits in sA buffer 0 (4352)
#define PITCH 68
#define ABUF (64 * PITCH)                  // 4352 floats per stage
#define SA_OFF 384
#define SB_OFF (SA_OFF + 2 * ABUF)         // 9088
#define SMEM_FLOATS (SB_OFF + 2 * ABUF)    // 17792
#define SMEM_BYTES (SMEM_FLOATS * 4)       // 71168 B -> 3 CTAs/SM

// ---- tf32 / async helpers ----
__device__ __forceinline__ unsigned f2tf(float x) {
    unsigned r;
    asm("cvt.rna.tf32.f32 %0, %1;" : "=r"(r) : "f"(x));
    return r;
}
__device__ __forceinline__ void split_tf32(float x, unsigned& hi, unsigned& lo) {
    hi = f2tf(x);
    lo = f2tf(x - __uint_as_float(hi));
}
__device__ __forceinline__ void mma_tf32(float* c,
                                         unsigned a0, unsigned a1, unsigned a2, unsigned a3,
                                         unsigned b0, unsigned b1) {
    asm volatile(
        "mma.sync.aligned.m16n8k8.row.col.f32.tf32.tf32.f32 "
        "{%0,%1,%2,%3}, {%4,%5,%6,%7}, {%8,%9}, {%0,%1,%2,%3};"
        : "+f"(c[0]), "+f"(c[1]), "+f"(c[2]), "+f"(c[3])
        : "r"(a0), "r"(a1), "r"(a2), "r"(a3), "r"(b0), "r"(b1));
}
__device__ __forceinline__ unsigned su32(const void* p) {
    return (unsigned)__cvta_generic_to_shared(p);
}
#define CP16(dst, src) asm volatile("cp.async.cg.shared.global [%0], [%1], 16;" :: "r"(dst), "l"(src))
#define CP_COMMIT()    asm volatile("cp.async.commit_group;" ::: "memory")
#define CP_WAIT1()     asm volatile("cp.async.wait_group 1;" ::: "memory")
#define CP_WAIT0()     asm volatile("cp.async.wait_group 0;" ::: "memory")

// ---------------------------------------------------------------------------
// Uniform fused kernel: 64-row GEMM+softmax tile + fill share per CTA,
// cp.async double-buffered raw staging; normalization folded into epilogue.
// ---------------------------------------------------------------------------
__global__ __launch_bounds__(256, 3)
void fused_kernel(const float* __restrict__ states,
                  const float* __restrict__ patterns,
                  const float* __restrict__ tw_in,
                  float* __restrict__ out) {
    extern __shared__ float smem[];
    int bid = blockIdx.x;
    int tid = threadIdx.x;

    long long rowBase = (long long)bid * 64;
    const float* A = states + rowBase * DD;

    float* sNorm = smem;            // [64]
    float* sInv  = smem + 64;       // [64]
    float* sTmp  = smem + 128;      // [256]
    float* sA    = smem + SA_OFF;   // [2][64][68]
    float* sB    = smem + SB_OFF;   // [2][64][68]

    // ---- hoisted route-fill value (column == 4*tid for all our stores) ----
    float4 rv;
    {
        const float r = 1.0f / 1024.0f;
        int c = tid << 2;
        rv.x = -(float)(c + 0) * r;
        rv.y = -(float)(c + 1) * r;
        rv.z = -(float)(c + 2) * r;
        rv.w = -(float)(c + 3) * r;
    }
    float4* routes4 = (float4*)(out + OFF_ROUTES) + (long long)bid * 16384 + tid;

    // ---- small fills: 16 float4 of routing + 16 of tw per CTA ----
    if (tid < 16) {
        const float r = 1.0f / 1024.0f;
        ((float4*)(out + OFF_ROUTING))[bid * 16 + tid] = make_float4(r, r, r, r);
    } else if (tid < 32) {
        int i4 = bid * 16 + (tid - 16);
        ((float4*)(out + OFF_TW))[i4] = ((const float4*)tw_in)[i4];
    }

    // ---- cp.async staging addresses (4 A-segs + 4 B-segs per thread) ----
    int srow = tid >> 4;           // 0..15 base row (rows srow, srow+16, srow+32, srow+48)
    int sseg = tid & 15;           // 16B segment within 64-float row
    const float* aSrc = A + (long long)srow * DD + sseg * 4;
    const float* bSrc = patterns + srow * DD + sseg * 4;
    unsigned aDst = su32(sA + srow * PITCH + sseg * 4);
    unsigned bDst = su32(sB + srow * PITCH + sseg * 4);
    const int rstep = 16 * DD;            // 16 rows in gmem
    const unsigned sstep = 16 * PITCH * 4; // 16 rows in smem (bytes)

    // prologue: issue chunk 0 into buffer 0
    #pragma unroll
    for (int j = 0; j < 4; j++) {
        CP16(aDst + j * sstep, aSrc + j * rstep);
        CP16(bDst + j * sstep, bSrc + j * rstep);
    }
    CP_COMMIT();

    // ---- pattern norm partials while chunk 0 is in flight ----
    {
        int p = tid >> 2, q = tid & 3;
        const float4* pv = (const float4*)(patterns + p * DD + q * 64);
        float ss = 0.0f;
        #pragma unroll
        for (int i = 0; i < 16; i++) {
            float4 v = pv[i];
            ss = fmaf(v.x, v.x, fmaf(v.y, v.y, fmaf(v.z, v.z, fmaf(v.w, v.w, ss))));
        }
        sTmp[tid] = ss;
    }

    int w    = tid >> 5;     // warp 0..7
    int lane = tid & 31;
    int g    = lane >> 2;    // group id 0..7
    int tig  = lane & 3;     // thread in group
    int wr   = w & 3;        // row-block (rows wr*16 .. +15)
    int wc   = w >> 2;       // col-half  (cols wc*32 .. +31)

    float acc[4][4];
    #pragma unroll
    for (int nb = 0; nb < 4; nb++)
        #pragma unroll
        for (int i = 0; i < 4; i++) acc[nb][i] = 0.0f;

    for (int c = 0; c < 4; c++) {       // 4 chunks of K=64
        if (c < 3) {
            unsigned boff = ((c + 1) & 1) * ABUF * 4;
            int koff = (c + 1) * 64;
            #pragma unroll
            for (int j = 0; j < 4; j++) {
                CP16(aDst + boff + j * sstep, aSrc + koff + j * rstep);
                CP16(bDst + boff + j * sstep, bSrc + koff + j * rstep);
            }
            CP_COMMIT();
            CP_WAIT1();
        } else {
            CP_WAIT0();
        }
        __syncthreads();

        if (c == 0 && tid < 64) {
            float s = sTmp[tid * 4] + sTmp[tid * 4 + 1] + sTmp[tid * 4 + 2] + sTmp[tid * 4 + 3];
            sNorm[tid] = 1.0f / fmaxf(sqrtf(s), 1e-12f);
        }

        // interleaved route-fill: 16 independent streaming stores per thread
        #pragma unroll
        for (int j = 0; j < 16; j++)
            __stcs(routes4 + (c * 16 + j) * 256, rv);

        const float* aRow0 = sA + (c & 1) * ABUF + (wr * 16 + g) * PITCH;
        const float* aRow8 = aRow0 + 8 * PITCH;
        const float* bBase = sB + (c & 1) * ABUF;
        #pragma unroll
        for (int ks = 0; ks < 8; ks++) {
            int k0 = ks * 8;
            unsigned ah0, ah1, ah2, ah3, al0, al1, al2, al3;
            split_tf32(aRow0[k0 + tig],     ah0, al0);
            split_tf32(aRow8[k0 + tig],     ah1, al1);
            split_tf32(aRow0[k0 + tig + 4], ah2, al2);
            split_tf32(aRow8[k0 + tig + 4], ah3, al3);
            #pragma unroll
            for (int nb = 0; nb < 4; nb++) {
                const float* bp = bBase + (wc * 32 + nb * 8 + g) * PITCH + k0 + tig;
                unsigned bh0, bl0, bh1, bl1;
                split_tf32(bp[0], bh0, bl0);
                split_tf32(bp[4], bh1, bl1);
                mma_tf32(acc[nb], ah0, ah1, ah2, ah3, bh0, bh1);
                mma_tf32(acc[nb], ah0, ah1, ah2, ah3, bl0, bl1);
                mma_tf32(acc[nb], al0, al1, al2, al3, bh0, bh1);
            }
        }
        __syncthreads();
    }

    // ================ epilogue: scale by pattern norms, softmax per row ================
    float* sS = sA;   // overlay [64][66] in buffer 0
    {
        int r0 = wr * 16 + g;
        #pragma unroll
        for (int nb = 0; nb < 4; nb++) {
            int col = wc * 32 + nb * 8 + 2 * tig;
            float inv0 = sNorm[col], inv1 = sNorm[col + 1];
            *(float2*)&sS[r0 * 66 + col]       = make_float2(acc[nb][0] * inv0, acc[nb][1] * inv1);
            *(float2*)&sS[(r0 + 8) * 66 + col] = make_float2(acc[nb][2] * inv0, acc[nb][3] * inv1);
        }
    }
    __syncthreads();

    // 4 threads per row: thread (row, q) handles 16 patterns; shfl-combine.
    {
        int row = tid >> 2;
        int q   = tid & 3;
        float* rowp = &sS[row * 66 + q * 16];
        float mx = -1e30f;
        #pragma unroll
        for (int p = 0; p < 16; p++) mx = fmaxf(mx, rowp[p]);
        mx = fmaxf(mx, __shfl_xor_sync(0xFFFFFFFFu, mx, 1));
        mx = fmaxf(mx, __shfl_xor_sync(0xFFFFFFFFu, mx, 2));
        mx *= TINV;
        float sum = 0.0f;
        #pragma unroll
        for (int p = 0; p < 16; p++) {
            float e = __expf(rowp[p] * TINV - mx);
            rowp[p] = e;
            sum += e;
        }
        sum += __shfl_xor_sync(0xFFFFFFFFu, sum, 1);
        sum += __shfl_xor_sync(0xFFFFFFFFu, sum, 2);
        if (q == 0) sInv[row] = 1.0f / sum;
    }
    __syncthreads();

    // coalesced streaming store of the 64x64 tile
    float* O = out + OFF_PS + rowBase * PP;
    #pragma unroll
    for (int j = 0; j < 4; j++) {
        int i = tid + j * 256;
        int row = i >> 4, pq = (i & 15) << 2;
        float inv = sInv[row];
        float4 v = make_float4(sS[row * 66 + pq + 0] * inv,
                               sS[row * 66 + pq + 1] * inv,
                               sS[row * 66 + pq + 2] * inv,
                               sS[row * 66 + pq + 3] * inv);
        __stcs((float4*)&O[row * PP + pq], v);
    }
}

extern "C" void kernel_launch(void* const* d_in, const int* in_sizes, int n_in,
                              void* d_out, int out_size) {
    const float* states   = (const float*)d_in[0];  // (4,16,1024,256)
    const float* patterns = (const float*)d_in[1];  // (64,256)
    const float* tw       = (const float*)d_in[2];  // (16,64,64)
    float* out = (float*)d_out;

    cudaFuncSetAttribute(fused_kernel,
                         cudaFuncAttributeMaxDynamicSharedMemorySize,
                         SMEM_BYTES);

    fused_kernel<<<GRID_TOTAL, 256, SMEM_BYTES>>>(states, patterns, tw, out);
}

// round 14
// speedup vs baseline: 1.2696x; 1.0071x over previous
#include <cuda_runtime.h>
#include <math.h>
#include <stdint.h>

// Problem constants
#define DD 256
#define PP 64
#define TINV 10.0f

// Output offsets (floats): routing(65536) | routes(67108864) | tw(65536) | ps(4194304)
#define OFF_ROUTING 0LL
#define OFF_ROUTES  65536LL
#define OFF_TW      67174400LL
#define OFF_PS      67239936LL

#define GRID_TOTAL 1024     // uniform CTAs: 64-row GEMM tile + 1/1024 of all fills

// smem (floats):
//  [0,64) sNorm | [64,128) sInv | [128,384) tmp partials
//  [384, 384+2*64*68)  sA double buffer (raw fp32)
//  [9088, 9088+2*64*68) sB double buffer (raw fp32)
// epilogue overlay: sS[64][66] (4224) fits in sA buffer 0 (4352)
#define PITCH 68
#define ABUF (64 * PITCH)                  // 4352 floats per stage
#define SA_OFF 384
#define SB_OFF (SA_OFF + 2 * ABUF)         // 9088
#define SMEM_FLOATS (SB_OFF + 2 * ABUF)    // 17792
#define SMEM_BYTES (SMEM_FLOATS * 4)       // 71168 B -> 3 CTAs/SM

// ---- tf32 / async helpers ----
__device__ __forceinline__ unsigned f2tf(float x) {
    unsigned r;
    asm("cvt.rna.tf32.f32 %0, %1;" : "=r"(r) : "f"(x));
    return r;
}
__device__ __forceinline__ void split_tf32(float x, unsigned& hi, unsigned& lo) {
    hi = f2tf(x);
    lo = f2tf(x - __uint_as_float(hi));
}
__device__ __forceinline__ void mma_tf32(float* c,
                                         unsigned a0, unsigned a1, unsigned a2, unsigned a3,
                                         unsigned b0, unsigned b1) {
    asm volatile(
        "mma.sync.aligned.m16n8k8.row.col.f32.tf32.tf32.f32 "
        "{%0,%1,%2,%3}, {%4,%5,%6,%7}, {%8,%9}, {%0,%1,%2,%3};"
        : "+f"(c[0]), "+f"(c[1]), "+f"(c[2]), "+f"(c[3])
        : "r"(a0), "r"(a1), "r"(a2), "r"(a3), "r"(b0), "r"(b1));
}
__device__ __forceinline__ unsigned su32(const void* p) {
    return (unsigned)__cvta_generic_to_shared(p);
}
#define CP16(dst, src) asm volatile("cp.async.cg.shared.global [%0], [%1], 16;" :: "r"(dst), "l"(src))
#define CP_COMMIT()    asm volatile("cp.async.commit_group;" ::: "memory")
#define CP_WAIT1()     asm volatile("cp.async.wait_group 1;" ::: "memory")
#define CP_WAIT0()     asm volatile("cp.async.wait_group 0;" ::: "memory")

// ---------------------------------------------------------------------------
// Uniform fused kernel: 64-row GEMM+softmax tile + fill share per CTA.
// cp.async double-buffered staging; route stores issued INSIDE the load-wait
// window so DRAM write issue overlaps DRAM read latency.
// ---------------------------------------------------------------------------
__global__ __launch_bounds__(256, 3)
void fused_kernel(const float* __restrict__ states,
                  const float* __restrict__ patterns,
                  const float* __restrict__ tw_in,
                  float* __restrict__ out) {
    extern __shared__ float smem[];
    int bid = blockIdx.x;
    int tid = threadIdx.x;

    long long rowBase = (long long)bid * 64;
    const float* A = states + rowBase * DD;

    float* sNorm = smem;            // [64]
    float* sInv  = smem + 64;       // [64]
    float* sTmp  = smem + 128;      // [256]
    float* sA    = smem + SA_OFF;   // [2][64][68]
    float* sB    = smem + SB_OFF;   // [2][64][68]

    // ---- hoisted route-fill value (column == 4*tid for all our stores) ----
    float4 rv;
    {
        const float r = 1.0f / 1024.0f;
        int c = tid << 2;
        rv.x = -(float)(c + 0) * r;
        rv.y = -(float)(c + 1) * r;
        rv.z = -(float)(c + 2) * r;
        rv.w = -(float)(c + 3) * r;
    }
    float4* routes4 = (float4*)(out + OFF_ROUTES) + (long long)bid * 16384 + tid;

    // ---- small fills first: pure stores, fully independent of everything ----
    if (tid < 16) {
        const float r = 1.0f / 1024.0f;
        ((float4*)(out + OFF_ROUTING))[bid * 16 + tid] = make_float4(r, r, r, r);
    } else if (tid < 32) {
        int i4 = bid * 16 + (tid - 16);
        ((float4*)(out + OFF_TW))[i4] = ((const float4*)tw_in)[i4];
    }

    // ---- cp.async staging addresses (4 A-segs + 4 B-segs per thread) ----
    int srow = tid >> 4;           // base row (rows srow, srow+16, srow+32, srow+48)
    int sseg = tid & 15;           // 16B segment within 64-float row
    const float* aSrc = A + (long long)srow * DD + sseg * 4;
    const float* bSrc = patterns + srow * DD + sseg * 4;
    unsigned aDst = su32(sA + srow * PITCH + sseg * 4);
    unsigned bDst = su32(sB + srow * PITCH + sseg * 4);
    const int rstep = 16 * DD;             // 16 rows in gmem
    const unsigned sstep = 16 * PITCH * 4; // 16 rows in smem (bytes)

    // prologue: issue chunk 0 into buffer 0
    #pragma unroll
    for (int j = 0; j < 4; j++) {
        CP16(aDst + j * sstep, aSrc + j * rstep);
        CP16(bDst + j * sstep, bSrc + j * rstep);
    }
    CP_COMMIT();

    // ---- pattern norm partials while chunk 0 is in flight ----
    {
        int p = tid >> 2, q = tid & 3;
        const float4* pv = (const float4*)(patterns + p * DD + q * 64);
        float ss = 0.0f;
        #pragma unroll
        for (int i = 0; i < 16; i++) {
            float4 v = pv[i];
            ss = fmaf(v.x, v.x, fmaf(v.y, v.y, fmaf(v.z, v.z, fmaf(v.w, v.w, ss))));
        }
        sTmp[tid] = ss;
    }

    int w    = tid >> 5;     // warp 0..7
    int lane = tid & 31;
    int g    = lane >> 2;    // group id 0..7
    int tig  = lane & 3;     // thread in group
    int wr   = w & 3;        // row-block (rows wr*16 .. +15)
    int wc   = w >> 2;       // col-half  (cols wc*32 .. +31)

    float acc[4][4];
    #pragma unroll
    for (int nb = 0; nb < 4; nb++)
        #pragma unroll
        for (int i = 0; i < 4; i++) acc[nb][i] = 0.0f;

    for (int c = 0; c < 4; c++) {       // 4 chunks of K=64
        if (c < 3) {
            unsigned boff = ((c + 1) & 1) * ABUF * 4;
            int koff = (c + 1) * 64;
            #pragma unroll
            for (int j = 0; j < 4; j++) {
                CP16(aDst + boff + j * sstep, aSrc + koff + j * rstep);
                CP16(bDst + boff + j * sstep, bSrc + koff + j * rstep);
            }
            CP_COMMIT();
        }

        // route-fill stores DURING the load-wait window: independent of
        // staged data, so they drain while cp.async fills the next buffer.
        #pragma unroll
        for (int j = 0; j < 16; j++)
            __stcs(routes4 + (c * 16 + j) * 256, rv);

        if (c < 3) CP_WAIT1(); else CP_WAIT0();
        __syncthreads();

        if (c == 0 && tid < 64) {
            float s = sTmp[tid * 4] + sTmp[tid * 4 + 1] + sTmp[tid * 4 + 2] + sTmp[tid * 4 + 3];
            sNorm[tid] = 1.0f / fmaxf(sqrtf(s), 1e-12f);
        }

        const float* aRow0 = sA + (c & 1) * ABUF + (wr * 16 + g) * PITCH;
        const float* aRow8 = aRow0 + 8 * PITCH;
        const float* bBase = sB + (c & 1) * ABUF;
        #pragma unroll
        for (int ks = 0; ks < 8; ks++) {
            int k0 = ks * 8;
            unsigned ah0, ah1, ah2, ah3, al0, al1, al2, al3;
            split_tf32(aRow0[k0 + tig],     ah0, al0);
            split_tf32(aRow8[k0 + tig],     ah1, al1);
            split_tf32(aRow0[k0 + tig + 4], ah2, al2);
            split_tf32(aRow8[k0 + tig + 4], ah3, al3);
            #pragma unroll
            for (int nb = 0; nb < 4; nb++) {
                const float* bp = bBase + (wc * 32 + nb * 8 + g) * PITCH + k0 + tig;
                unsigned bh0, bl0, bh1, bl1;
                split_tf32(bp[0], bh0, bl0);
                split_tf32(bp[4], bh1, bl1);
                mma_tf32(acc[nb], ah0, ah1, ah2, ah3, bh0, bh1);
                mma_tf32(acc[nb], ah0, ah1, ah2, ah3, bl0, bl1);
                mma_tf32(acc[nb], al0, al1, al2, al3, bh0, bh1);
            }
        }
        __syncthreads();
    }

    // ================ epilogue: scale by pattern norms, softmax per row ================
    float* sS = sA;   // overlay [64][66] in buffer 0
    {
        int r0 = wr * 16 + g;
        #pragma unroll
        for (int nb = 0; nb < 4; nb++) {
            int col = wc * 32 + nb * 8 + 2 * tig;
            float inv0 = sNorm[col], inv1 = sNorm[col + 1];
            *(float2*)&sS[r0 * 66 + col]       = make_float2(acc[nb][0] * inv0, acc[nb][1] * inv1);
            *(float2*)&sS[(r0 + 8) * 66 + col] = make_float2(acc[nb][2] * inv0, acc[nb][3] * inv1);
        }
    }
    __syncthreads();

    // 4 threads per row: thread (row, q) handles 16 patterns; shfl-combine.
    {
        int row = tid >> 2;
        int q   = tid & 3;
        float* rowp = &sS[row * 66 + q * 16];
        float mx = -1e30f;
        #pragma unroll
        for (int p = 0; p < 16; p++) mx = fmaxf(mx, rowp[p]);
        mx = fmaxf(mx, __shfl_xor_sync(0xFFFFFFFFu, mx, 1));
        mx = fmaxf(mx, __shfl_xor_sync(0xFFFFFFFFu, mx, 2));
        mx *= TINV;
        float sum = 0.0f;
        #pragma unroll
        for (int p = 0; p < 16; p++) {
            float e = __expf(rowp[p] * TINV - mx);
            rowp[p] = e;
            sum += e;
        }
        sum += __shfl_xor_sync(0xFFFFFFFFu, sum, 1);
        sum += __shfl_xor_sync(0xFFFFFFFFu, sum, 2);
        if (q == 0) sInv[row] = 1.0f / sum;
    }
    __syncthreads();

    // coalesced streaming store of the 64x64 tile
    float* O = out + OFF_PS + rowBase * PP;
    #pragma unroll
    for (int j = 0; j < 4; j++) {
        int i = tid + j * 256;
        int row = i >> 4, pq = (i & 15) << 2;
        float inv = sInv[row];
        float4 v = make_float4(sS[row * 66 + pq + 0] * inv,
                               sS[row * 66 + pq + 1] * inv,
                               sS[row * 66 + pq + 2] * inv,
                               sS[row * 66 + pq + 3] * inv);
        __stcs((float4*)&O[row * PP + pq], v);
    }
}

extern "C" void kernel_launch(void* const* d_in, const int* in_sizes, int n_in,
                              void* d_out, int out_size) {
    const float* states   = (const float*)d_in[0];  // (4,16,1024,256)
    const float* patterns = (const float*)d_in[1];  // (64,256)
    const float* tw       = (const float*)d_in[2];  // (16,64,64)
    float* out = (float*)d_out;

    cudaFuncSetAttribute(fused_kernel,
                         cudaFuncAttributeMaxDynamicSharedMemorySize,
                         SMEM_BYTES);

    fused_kernel<<<GRID_TOTAL, 256, SMEM_BYTES>>>(states, patterns, tw, out);
}

// round 15
// speedup vs baseline: 1.2977x; 1.0221x over previous
#include <cuda_runtime.h>
#include <math.h>
#include <stdint.h>

// Problem constants
#define DD 256
#define PP 64
#define TINV 10.0f

// Output offsets (floats): routing(65536) | routes(67108864) | tw(65536) | ps(4194304)
#define OFF_ROUTING 0LL
#define OFF_ROUTES  65536LL
#define OFF_TW      67174400LL
#define OFF_PS      67239936LL

#define GRID_TOTAL 1024     // uniform CTAs: 64-row GEMM tile + 1/1024 of all fills

// smem (floats):
//  [0,64) sNorm | [64,128) sInv | [128,384) tmp partials
//  [384, 384+2*64*68)  sA double buffer (raw fp32)
//  [9088, 9088+2*64*68) sB double buffer (raw fp32)
// epilogue overlay: sS[64][66] (4224) fits in sA buffer 0 (4352)
#define PITCH 68
#define ABUF (64 * PITCH)                  // 4352 floats per stage
#define SA_OFF 384
#define SB_OFF (SA_OFF + 2 * ABUF)         // 9088
#define SMEM_FLOATS (SB_OFF + 2 * ABUF)    // 17792
#define SMEM_BYTES (SMEM_FLOATS * 4)       // 71168 B -> 3 CTAs/SM

// ---- tf32 / async helpers ----
__device__ __forceinline__ unsigned f2tf(float x) {
    unsigned r;
    asm("cvt.rna.tf32.f32 %0, %1;" : "=r"(r) : "f"(x));
    return r;
}
__device__ __forceinline__ void split_tf32(float x, unsigned& hi, unsigned& lo) {
    hi = f2tf(x);
    lo = f2tf(x - __uint_as_float(hi));
}
__device__ __forceinline__ void mma_tf32(float* c,
                                         unsigned a0, unsigned a1, unsigned a2, unsigned a3,
                                         unsigned b0, unsigned b1) {
    asm volatile(
        "mma.sync.aligned.m16n8k8.row.col.f32.tf32.tf32.f32 "
        "{%0,%1,%2,%3}, {%4,%5,%6,%7}, {%8,%9}, {%0,%1,%2,%3};"
        : "+f"(c[0]), "+f"(c[1]), "+f"(c[2]), "+f"(c[3])
        : "r"(a0), "r"(a1), "r"(a2), "r"(a3), "r"(b0), "r"(b1));
}
__device__ __forceinline__ unsigned su32(const void* p) {
    return (unsigned)__cvta_generic_to_shared(p);
}
#define CP16(dst, src) asm volatile("cp.async.cg.shared.global [%0], [%1], 16;" :: "r"(dst), "l"(src))
#define CP_COMMIT()    asm volatile("cp.async.commit_group;" ::: "memory")
#define CP_WAIT1()     asm volatile("cp.async.wait_group 1;" ::: "memory")
#define CP_WAIT0()     asm volatile("cp.async.wait_group 0;" ::: "memory")

// ---------------------------------------------------------------------------
// Uniform fused kernel: 64-row GEMM+softmax tile + fill share per CTA.
// cp.async double-buffered staging. Route stores: 8 in the load-wait window,
// 8 interleaved into the mma loop -> continuous DRAM write stream per CTA.
// ---------------------------------------------------------------------------
__global__ __launch_bounds__(256, 3)
void fused_kernel(const float* __restrict__ states,
                  const float* __restrict__ patterns,
                  const float* __restrict__ tw_in,
                  float* __restrict__ out) {
    extern __shared__ float smem[];
    int bid = blockIdx.x;
    int tid = threadIdx.x;

    long long rowBase = (long long)bid * 64;
    const float* A = states + rowBase * DD;

    float* sNorm = smem;            // [64]
    float* sInv  = smem + 64;       // [64]
    float* sTmp  = smem + 128;      // [256]
    float* sA    = smem + SA_OFF;   // [2][64][68]
    float* sB    = smem + SB_OFF;   // [2][64][68]

    // ---- hoisted route-fill value (column == 4*tid for all our stores) ----
    float4 rv;
    {
        const float r = 1.0f / 1024.0f;
        int c = tid << 2;
        rv.x = -(float)(c + 0) * r;
        rv.y = -(float)(c + 1) * r;
        rv.z = -(float)(c + 2) * r;
        rv.w = -(float)(c + 3) * r;
    }
    float4* routes4 = (float4*)(out + OFF_ROUTES) + (long long)bid * 16384 + tid;

    // ---- small fills first: pure stores, fully independent of everything ----
    if (tid < 16) {
        const float r = 1.0f / 1024.0f;
        ((float4*)(out + OFF_ROUTING))[bid * 16 + tid] = make_float4(r, r, r, r);
    } else if (tid < 32) {
        int i4 = bid * 16 + (tid - 16);
        ((float4*)(out + OFF_TW))[i4] = ((const float4*)tw_in)[i4];
    }

    // ---- cp.async staging addresses (4 A-segs + 4 B-segs per thread) ----
    int srow = tid >> 4;           // base row (rows srow, srow+16, srow+32, srow+48)
    int sseg = tid & 15;           // 16B segment within 64-float row
    const float* aSrc = A + (long long)srow * DD + sseg * 4;
    const float* bSrc = patterns + srow * DD + sseg * 4;
    unsigned aDst = su32(sA + srow * PITCH + sseg * 4);
    unsigned bDst = su32(sB + srow * PITCH + sseg * 4);
    const int rstep = 16 * DD;             // 16 rows in gmem
    const unsigned sstep = 16 * PITCH * 4; // 16 rows in smem (bytes)

    // prologue: issue chunk 0 into buffer 0
    #pragma unroll
    for (int j = 0; j < 4; j++) {
        CP16(aDst + j * sstep, aSrc + j * rstep);
        CP16(bDst + j * sstep, bSrc + j * rstep);
    }
    CP_COMMIT();

    // ---- pattern norm partials while chunk 0 is in flight ----
    {
        int p = tid >> 2, q = tid & 3;
        const float4* pv = (const float4*)(patterns + p * DD + q * 64);
        float ss = 0.0f;
        #pragma unroll
        for (int i = 0; i < 16; i++) {
            float4 v = pv[i];
            ss = fmaf(v.x, v.x, fmaf(v.y, v.y, fmaf(v.z, v.z, fmaf(v.w, v.w, ss))));
        }
        sTmp[tid] = ss;
    }

    int w    = tid >> 5;     // warp 0..7
    int lane = tid & 31;
    int g    = lane >> 2;    // group id 0..7
    int tig  = lane & 3;     // thread in group
    int wr   = w & 3;        // row-block (rows wr*16 .. +15)
    int wc   = w >> 2;       // col-half  (cols wc*32 .. +31)

    float acc[4][4];
    #pragma unroll
    for (int nb = 0; nb < 4; nb++)
        #pragma unroll
        for (int i = 0; i < 4; i++) acc[nb][i] = 0.0f;

    for (int c = 0; c < 4; c++) {       // 4 chunks of K=64
        if (c < 3) {
            unsigned boff = ((c + 1) & 1) * ABUF * 4;
            int koff = (c + 1) * 64;
            #pragma unroll
            for (int j = 0; j < 4; j++) {
                CP16(aDst + boff + j * sstep, aSrc + koff + j * rstep);
                CP16(bDst + boff + j * sstep, bSrc + koff + j * rstep);
            }
            CP_COMMIT();
        }

        // route-fill stores in the load-wait window (8 of 16 this chunk)
        #pragma unroll
        for (int j = 0; j < 8; j++)
            __stcs(routes4 + (c * 16 + j) * 256, rv);

        if (c < 3) CP_WAIT1(); else CP_WAIT0();
        __syncthreads();

        if (c == 0 && tid < 64) {
            float s = sTmp[tid * 4] + sTmp[tid * 4 + 1] + sTmp[tid * 4 + 2] + sTmp[tid * 4 + 3];
            sNorm[tid] = 1.0f / fmaxf(sqrtf(s), 1e-12f);
        }

        const float* aRow0 = sA + (c & 1) * ABUF + (wr * 16 + g) * PITCH;
        const float* aRow8 = aRow0 + 8 * PITCH;
        const float* bBase = sB + (c & 1) * ABUF;
        #pragma unroll
        for (int ks = 0; ks < 8; ks++) {
            int k0 = ks * 8;
            // one route store per ks: keeps write stream alive through mma phase
            __stcs(routes4 + (c * 16 + 8 + ks) * 256, rv);
            unsigned ah0, ah1, ah2, ah3, al0, al1, al2, al3;
            split_tf32(aRow0[k0 + tig],     ah0, al0);
            split_tf32(aRow8[k0 + tig],     ah1, al1);
            split_tf32(aRow0[k0 + tig + 4], ah2, al2);
            split_tf32(aRow8[k0 + tig + 4], ah3, al3);
            #pragma unroll
            for (int nb = 0; nb < 4; nb++) {
                const float* bp = bBase + (wc * 32 + nb * 8 + g) * PITCH + k0 + tig;
                unsigned bh0, bl0, bh1, bl1;
                split_tf32(bp[0], bh0, bl0);
                split_tf32(bp[4], bh1, bl1);
                mma_tf32(acc[nb], ah0, ah1, ah2, ah3, bh0, bh1);
                mma_tf32(acc[nb], ah0, ah1, ah2, ah3, bl0, bl1);
                mma_tf32(acc[nb], al0, al1, al2, al3, bh0, bh1);
            }
        }
        __syncthreads();
    }

    // ================ epilogue: scale by pattern norms, softmax per row ================
    float* sS = sA;   // overlay [64][66] in buffer 0
    {
        int r0 = wr * 16 + g;
        #pragma unroll
        for (int nb = 0; nb < 4; nb++) {
            int col = wc * 32 + nb * 8 + 2 * tig;
            float inv0 = sNorm[col], inv1 = sNorm[col + 1];
            *(float2*)&sS[r0 * 66 + col]       = make_float2(acc[nb][0] * inv0, acc[nb][1] * inv1);
            *(float2*)&sS[(r0 + 8) * 66 + col] = make_float2(acc[nb][2] * inv0, acc[nb][3] * inv1);
        }
    }
    __syncthreads();

    // 4 threads per row: thread (row, q) handles 16 patterns; shfl-combine.
    {
        int row = tid >> 2;
        int q   = tid & 3;
        float* rowp = &sS[row * 66 + q * 16];
        float mx = -1e30f;
        #pragma unroll
        for (int p = 0; p < 16; p++) mx = fmaxf(mx, rowp[p]);
        mx = fmaxf(mx, __shfl_xor_sync(0xFFFFFFFFu, mx, 1));
        mx = fmaxf(mx, __shfl_xor_sync(0xFFFFFFFFu, mx, 2));
        mx *= TINV;
        float sum = 0.0f;
        #pragma unroll
        for (int p = 0; p < 16; p++) {
            float e = __expf(rowp[p] * TINV - mx);
            rowp[p] = e;
            sum += e;
        }
        sum += __shfl_xor_sync(0xFFFFFFFFu, sum, 1);
        sum += __shfl_xor_sync(0xFFFFFFFFu, sum, 2);
        if (q == 0) sInv[row] = 1.0f / sum;
    }
    __syncthreads();

    // coalesced streaming store of the 64x64 tile
    float* O = out + OFF_PS + rowBase * PP;
    #pragma unroll
    for (int j = 0; j < 4; j++) {
        int i = tid + j * 256;
        int row = i >> 4, pq = (i & 15) << 2;
        float inv = sInv[row];
        float4 v = make_float4(sS[row * 66 + pq + 0] * inv,
                               sS[row * 66 + pq + 1] * inv,
                               sS[row * 66 + pq + 2] * inv,
                               sS[row * 66 + pq + 3] * inv);
        __stcs((float4*)&O[row * PP + pq], v);
    }
}

extern "C" void kernel_launch(void* const* d_in, const int* in_sizes, int n_in,
                              void* d_out, int out_size) {
    const float* states   = (const float*)d_in[0];  // (4,16,1024,256)
    const float* patterns = (const float*)d_in[1];  // (64,256)
    const float* tw       = (const float*)d_in[2];  // (16,64,64)
    float* out = (float*)d_out;

    cudaFuncSetAttribute(fused_kernel,
                         cudaFuncAttributeMaxDynamicSharedMemorySize,
                         SMEM_BYTES);

    fused_kernel<<<GRID_TOTAL, 256, SMEM_BYTES>>>(states, patterns, tw, out);
}